// round 3
// baseline (speedup 1.0000x reference)
#include <cuda_runtime.h>
#include <math.h>

#define BLOCK 256
#define GPT 2                 // float4 groups per thread -> 8 samples/thread
#define SMEM_SEGS 256         // segments stageable per block (8 KB)

__device__ __forceinline__ void seg_coeffs_from_pts(
    const float2* __restrict__ ctrl, const float2* __restrict__ joint, int s,
    float4& a, float4& b) {
    float2 p0 = joint[s];
    float2 p3 = joint[s + 1];
    float2 p1 = ctrl[2 * s];
    float2 p2 = ctrl[2 * s + 1];
    // power-basis coeffs: c0..c3 (Bezier matrix folded in)
    a.x = p0.x;                                        // c0.x
    a.y = p0.y;                                        // c0.y
    a.z = 3.0f * (p1.x - p0.x);                        // c1.x
    a.w = 3.0f * (p1.y - p0.y);                        // c1.y
    b.x = 3.0f * p0.x - 6.0f * p1.x + 3.0f * p2.x;     // c2.x
    b.y = 3.0f * p0.y - 6.0f * p1.y + 3.0f * p2.y;     // c2.y
    b.z = -p0.x + 3.0f * p1.x - 3.0f * p2.x + p3.x;    // c3.x
    b.w = -p0.y + 3.0f * p1.y - 3.0f * p2.y + p3.y;    // c3.y
}

__device__ __forceinline__ void eval_pair(const float4& a, const float4& b,
                                          float l, float& x, float& y) {
    float l2 = l * l;
    float l3 = l2 * l;
    x = fmaf(b.z, l3, fmaf(b.x, l2, fmaf(a.z, l, a.x)));
    y = fmaf(b.w, l3, fmaf(b.y, l2, fmaf(a.w, l, a.y)));
}

__global__ void __launch_bounds__(BLOCK)
spline_fused_kernel(const float4* __restrict__ t4,
                    const float2* __restrict__ ctrl,
                    const float2* __restrict__ joint,
                    float4* __restrict__ out4,
                    int n4, float Sf, int S) {
    __shared__ float4 s_coeff[2 * SMEM_SEGS];
    __shared__ int s_range[2];

    const int tid = threadIdx.x;
    const int base = blockIdx.x * (BLOCK * GPT);
    const int i0 = base + tid;
    const int i1 = base + BLOCK + tid;
    const bool v0 = i0 < n4;
    const bool v1 = i1 < n4;

    float4 z = make_float4(0.f, 0.f, 0.f, 0.f);
    float4 tv0 = v0 ? __ldcs(t4 + i0) : z;
    float4 tv1 = v1 ? __ldcs(t4 + i1) : z;

    float ts[8] = {tv0.x, tv0.y, tv0.z, tv0.w, tv1.x, tv1.y, tv1.z, tv1.w};
    int   seg[8];
    float lt[8];
#pragma unroll
    for (int j = 0; j < 8; j++) {
        float tc = fminf(ts[j], 1.0f);
        float u = Sf * tc;
        int sg = (int)floorf(u);
        float l = u - (float)sg;
        if (sg >= S) { sg = S - 1; l = 1.0f; }
        seg[j] = sg;
        lt[j] = l;
    }

    // t sorted: block min = thread 0 / sample 0; block max = owner of last
    // valid group, its last sample.
    int lastIdx = min(base + BLOCK * GPT - 1, n4 - 1);
    if (tid == 0)            s_range[0] = seg[0];
    if (v0 && i0 == lastIdx) s_range[1] = seg[3];
    if (v1 && i1 == lastIdx) s_range[1] = seg[7];
    __syncthreads();

    int lo = s_range[0];
    int cnt = s_range[1] - lo + 1;

    if (cnt <= SMEM_SEGS) {            // block-uniform branch
        for (int k = tid; k < cnt; k += BLOCK) {
            float4 a, b;
            seg_coeffs_from_pts(ctrl, joint, lo + k, a, b);
            s_coeff[2 * k + 0] = a;
            s_coeff[2 * k + 1] = b;
        }
        __syncthreads();

        float rx[8], ry[8];
#pragma unroll
        for (int j = 0; j < 8; j++) {
            int rel = seg[j] - lo;
            float4 a = s_coeff[2 * rel + 0];
            float4 b = s_coeff[2 * rel + 1];
            eval_pair(a, b, lt[j], rx[j], ry[j]);
        }
        if (v0) {
            __stcs(out4 + 2 * i0 + 0, make_float4(rx[0], ry[0], rx[1], ry[1]));
            __stcs(out4 + 2 * i0 + 1, make_float4(rx[2], ry[2], rx[3], ry[3]));
        }
        if (v1) {
            __stcs(out4 + 2 * i1 + 0, make_float4(rx[4], ry[4], rx[5], ry[5]));
            __stcs(out4 + 2 * i1 + 1, make_float4(rx[6], ry[6], rx[7], ry[7]));
        }
    } else {
        // fallback: wide segment span (not hit for sorted uniform t); compute
        // coefficients per sample straight from global points (L2-cached).
        float rx[8], ry[8];
#pragma unroll
        for (int j = 0; j < 8; j++) {
            float4 a, b;
            seg_coeffs_from_pts(ctrl, joint, seg[j], a, b);
            eval_pair(a, b, lt[j], rx[j], ry[j]);
        }
        if (v0) {
            __stcs(out4 + 2 * i0 + 0, make_float4(rx[0], ry[0], rx[1], ry[1]));
            __stcs(out4 + 2 * i0 + 1, make_float4(rx[2], ry[2], rx[3], ry[3]));
        }
        if (v1) {
            __stcs(out4 + 2 * i1 + 0, make_float4(rx[4], ry[4], rx[5], ry[5]));
            __stcs(out4 + 2 * i1 + 1, make_float4(rx[6], ry[6], rx[7], ry[7]));
        }
    }
}

// Scalar tail for n % 4 != 0 (not hit for N = 8388608)
__global__ void spline_eval_tail(const float* __restrict__ t,
                                 const float2* __restrict__ ctrl,
                                 const float2* __restrict__ joint,
                                 float2* __restrict__ out,
                                 int start, int n, float Sf, int S) {
    int i = start + blockIdx.x * blockDim.x + threadIdx.x;
    if (i >= n) return;
    float tc = fminf(t[i], 1.0f);
    float u = Sf * tc;
    int sg = (int)floorf(u);
    float l = u - (float)sg;
    if (sg >= S) { sg = S - 1; l = 1.0f; }
    float4 a, b;
    seg_coeffs_from_pts(ctrl, joint, sg, a, b);
    float x, y;
    eval_pair(a, b, l, x, y);
    out[i] = make_float2(x, y);
}

extern "C" void kernel_launch(void* const* d_in, const int* in_sizes, int n_in,
                              void* d_out, int out_size) {
    const float* t = (const float*)d_in[0];
    const float2* ctrl = (const float2*)d_in[1];
    const float2* joint = (const float2*)d_in[2];

    int n = in_sizes[0];
    int S = in_sizes[2] / 2 - 1;

    int n4 = n / 4;
    if (n4 > 0) {
        int samplesPerBlock = BLOCK * GPT;
        int blocks = (n4 + samplesPerBlock - 1) / samplesPerBlock;
        spline_fused_kernel<<<blocks, BLOCK>>>((const float4*)t, ctrl, joint,
                                               (float4*)d_out, n4, (float)S, S);
    }
    int rem = n - n4 * 4;
    if (rem > 0) {
        spline_eval_tail<<<1, 128>>>(t, ctrl, joint, (float2*)d_out,
                                     n4 * 4, n, (float)S, S);
    }
}

// round 4
// speedup vs baseline: 1.0273x; 1.0273x over previous
#include <cuda_runtime.h>
#include <math.h>

#define MAX_S 4096
__device__ float4 g_coeffs[2 * MAX_S];

#define BLOCK 256
#define GPT 4                 // independent float4 t-loads per thread (MLP=4), 16 samples/thread

__global__ void spline_coeff_kernel(const float2* __restrict__ ctrl,
                                    const float2* __restrict__ joint,
                                    int S) {
    int s = blockIdx.x * blockDim.x + threadIdx.x;
    if (s >= S) return;
    float2 p0 = joint[s];
    float2 p3 = joint[s + 1];
    float2 p1 = ctrl[2 * s];
    float2 p2 = ctrl[2 * s + 1];

    float c1x = 3.0f * (p1.x - p0.x);
    float c1y = 3.0f * (p1.y - p0.y);
    float c2x = 3.0f * p0.x - 6.0f * p1.x + 3.0f * p2.x;
    float c2y = 3.0f * p0.y - 6.0f * p1.y + 3.0f * p2.y;
    float c3x = -p0.x + 3.0f * p1.x - 3.0f * p2.x + p3.x;
    float c3y = -p0.y + 3.0f * p1.y - 3.0f * p2.y + p3.y;

    g_coeffs[2 * s + 0] = make_float4(p0.x, p0.y, c1x, c1y);
    g_coeffs[2 * s + 1] = make_float4(c2x, c2y, c3x, c3y);
}

__global__ void __launch_bounds__(BLOCK)
spline_eval_kernel(const float4* __restrict__ t4,
                   float4* __restrict__ out4,
                   int n4, float Sf, int S) {
    const int base = blockIdx.x * (BLOCK * GPT) + threadIdx.x;

    // Front-batched independent loads: MLP = 4
    float4 tv[GPT];
    bool v[GPT];
#pragma unroll
    for (int k = 0; k < GPT; k++) {
        int i = base + k * BLOCK;
        v[k] = (i < n4);
        tv[k] = v[k] ? t4[i] : make_float4(0.f, 0.f, 0.f, 0.f);
    }

#pragma unroll
    for (int k = 0; k < GPT; k++) {
        if (!v[k]) continue;
        int i = base + k * BLOCK;
        float ts[4] = {tv[k].x, tv[k].y, tv[k].z, tv[k].w};
        float rx[4], ry[4];
#pragma unroll
        for (int j = 0; j < 4; j++) {
            float tc = fminf(ts[j], 1.0f);
            float u = Sf * tc;
            int sg = (int)floorf(u);
            float l = u - (float)sg;
            if (sg >= S) { sg = S - 1; l = 1.0f; }

            float4 a = __ldg(&g_coeffs[2 * sg + 0]);   // c0.x c0.y c1.x c1.y
            float4 b = __ldg(&g_coeffs[2 * sg + 1]);   // c2.x c2.y c3.x c3.y

            float l2 = l * l;
            float l3 = l2 * l;
            rx[j] = fmaf(b.z, l3, fmaf(b.x, l2, fmaf(a.z, l, a.x)));
            ry[j] = fmaf(b.w, l3, fmaf(b.y, l2, fmaf(a.w, l, a.y)));
        }
        // Streaming stores: evict-first so output doesn't thrash t in L2
        __stcs(out4 + 2 * i + 0, make_float4(rx[0], ry[0], rx[1], ry[1]));
        __stcs(out4 + 2 * i + 1, make_float4(rx[2], ry[2], rx[3], ry[3]));
    }
}

// Scalar tail for n % 4 != 0 (not hit for N = 8388608)
__global__ void spline_eval_tail(const float* __restrict__ t,
                                 float2* __restrict__ out,
                                 int start, int n, float Sf, int S) {
    int i = start + blockIdx.x * blockDim.x + threadIdx.x;
    if (i >= n) return;
    float tc = fminf(t[i], 1.0f);
    float u = Sf * tc;
    int sg = (int)floorf(u);
    float l = u - (float)sg;
    if (sg >= S) { sg = S - 1; l = 1.0f; }
    float4 a = __ldg(&g_coeffs[2 * sg + 0]);
    float4 b = __ldg(&g_coeffs[2 * sg + 1]);
    float l2 = l * l;
    float l3 = l2 * l;
    float x = fmaf(b.z, l3, fmaf(b.x, l2, fmaf(a.z, l, a.x)));
    float y = fmaf(b.w, l3, fmaf(b.y, l2, fmaf(a.w, l, a.y)));
    out[i] = make_float2(x, y);
}

extern "C" void kernel_launch(void* const* d_in, const int* in_sizes, int n_in,
                              void* d_out, int out_size) {
    const float* t = (const float*)d_in[0];
    const float2* ctrl = (const float2*)d_in[1];
    const float2* joint = (const float2*)d_in[2];

    int n = in_sizes[0];
    int S = in_sizes[2] / 2 - 1;

    {
        int threads = 256;
        int blocks = (S + threads - 1) / threads;
        spline_coeff_kernel<<<blocks, threads>>>(ctrl, joint, S);
    }

    int n4 = n / 4;
    if (n4 > 0) {
        int perBlock = BLOCK * GPT;
        int blocks = (n4 + perBlock - 1) / perBlock;
        spline_eval_kernel<<<blocks, BLOCK>>>((const float4*)t, (float4*)d_out,
                                              n4, (float)S, S);
    }
    int rem = n - n4 * 4;
    if (rem > 0) {
        spline_eval_tail<<<1, 128>>>(t, (float2*)d_out, n4 * 4, n, (float)S, S);
    }
}